// round 1
// baseline (speedup 1.0000x reference)
#include <cuda_runtime.h>

#define IN_F  512
#define OUT_F 512
#define NBAT  8192
#define KC    12      // 1 (raw x for base weight) + 11 spline bases

// Compute [x_raw, B_0(xc)..B_10(xc)] exactly following the reference recursion,
// with the uniform-knot divisions folded to reciprocal constants.
__device__ __forceinline__ void aug_features(float xr, float* bb) {
    float xc = fminf(fmaxf(xr, -2.0f), 2.0f);
    float g[15];
#pragma unroll
    for (int m = 0; m < 15; ++m) g[m] = fmaf((float)m, 2.0f / 14.0f, -1.0f);
    float b[14];
#pragma unroll
    for (int m = 0; m < 14; ++m) b[m] = (xc >= g[m] && xc < g[m + 1]) ? 1.0f : 0.0f;
#pragma unroll
    for (int k = 1; k <= 3; ++k) {
        float inv = 7.0f / (float)k;   // all denominators are k/7 on a uniform grid
#pragma unroll
        for (int m = 0; m < 14 - k; ++m) {
            b[m] = (xc - g[m]) * inv * b[m] + (g[m + k + 1] - xc) * inv * b[m + 1];
        }
    }
    bb[0] = xr;                        // base path uses UNclipped x
#pragma unroll
    for (int j = 0; j < 11; ++j) bb[1 + j] = b[j];
}

__global__ __launch_bounds__(256, 2)
void kan_fused_fp32(const float* __restrict__ x,
                    const float* __restrict__ bw,
                    const float* __restrict__ sw,
                    float* __restrict__ out) {
    __shared__ float As[KC][128];      // [c][b-in-tile]
    __shared__ float Ws[KC][128];      // [c][o-in-tile]

    const int tid = threadIdx.x;
    const int tx = tid & 15;           // o direction (16)
    const int ty = tid >> 4;           // b direction (16)
    const int bBase = blockIdx.y * 128;
    const int oBase = blockIdx.x * 128;

    float acc[8][8];
#pragma unroll
    for (int m = 0; m < 8; ++m)
#pragma unroll
        for (int n = 0; n < 8; ++n) acc[m][n] = 0.0f;

    for (int i = 0; i < IN_F; ++i) {
        // --- stage augmented activations for this input feature ---
        if (tid < 128) {
            float bb[KC];
            aug_features(x[(size_t)(bBase + tid) * IN_F + i], bb);
#pragma unroll
            for (int c = 0; c < KC; ++c) As[c][tid] = bb[c];
        }
        // --- stage augmented weights: W[o, c] for this i ---
#pragma unroll
        for (int r = tid; r < 128 * KC; r += 256) {   // exactly 6 iters/thread
            int o = r / KC;
            int c = r - o * KC;
            int og = oBase + o;
            Ws[c][o] = (c == 0) ? bw[(size_t)og * IN_F + i]
                                : sw[((size_t)og * IN_F + i) * 11 + (c - 1)];
        }
        __syncthreads();

        // --- 12-deep rank-1 updates, 8x8 register tile per thread ---
#pragma unroll
        for (int c = 0; c < KC; ++c) {
            float4 a0 = *(const float4*)&As[c][ty * 8];
            float4 a1 = *(const float4*)&As[c][ty * 8 + 4];
            float4 w0 = *(const float4*)&Ws[c][tx * 8];
            float4 w1 = *(const float4*)&Ws[c][tx * 8 + 4];
            float a[8] = {a0.x, a0.y, a0.z, a0.w, a1.x, a1.y, a1.z, a1.w};
            float w[8] = {w0.x, w0.y, w0.z, w0.w, w1.x, w1.y, w1.z, w1.w};
#pragma unroll
            for (int m = 0; m < 8; ++m)
#pragma unroll
                for (int n = 0; n < 8; ++n)
                    acc[m][n] = fmaf(a[m], w[n], acc[m][n]);
        }
        __syncthreads();
    }

    // --- epilogue ---
#pragma unroll
    for (int m = 0; m < 8; ++m) {
        int b = bBase + ty * 8 + m;
        float4* p = (float4*)&out[(size_t)b * OUT_F + oBase + tx * 8];
        p[0] = make_float4(acc[m][0], acc[m][1], acc[m][2], acc[m][3]);
        p[1] = make_float4(acc[m][4], acc[m][5], acc[m][6], acc[m][7]);
    }
}

extern "C" void kernel_launch(void* const* d_in, const int* in_sizes, int n_in,
                              void* d_out, int out_size) {
    const float* x  = (const float*)d_in[0];   // (8192, 512)
    const float* bw = (const float*)d_in[1];   // (512, 512)
    const float* sw = (const float*)d_in[2];   // (512, 512, 11)
    float* out = (float*)d_out;                // (8192, 512)

    dim3 grid(OUT_F / 128, NBAT / 128);        // (4, 64)
    kan_fused_fp32<<<grid, 256>>>(x, bw, sw, out);
}

// round 6
// speedup vs baseline: 2.2946x; 2.2946x over previous
#include <cuda_runtime.h>
#include <cuda_bf16.h>
#include <cstdint>

#define IN_F   512
#define OUT_F  512
#define NBAT   8192
#define NFEAT  12                      // 1 raw x + 11 spline bases
#define SLOTS  3                       // bf16 split: A=[hi,lo,hi], B=[hi,hi,lo]
#define KAUG   (IN_F * NFEAT * SLOTS)  // 18432
#define KCHUNK 32                      // bf16 elems per pipeline chunk (64 B)
#define NCH    (KAUG / KCHUNK)         // 576
#define STG    4
#define M_TILE 128
#define N_TILE 256
#define ROWB   (KAUG * 2)              // global row stride in bytes
#define STAGE_BYTES (M_TILE * 64 + N_TILE * 64)   // 8KB A + 16KB B = 24576
#define SMEM_TOTAL  (STG * STAGE_BYTES)           // 98304

// ---------------- scratch (device globals: allocation-free) ----------------
__device__ __nv_bfloat16 g_A[(size_t)NBAT * KAUG];    // 302 MB
__device__ __nv_bfloat16 g_B[(size_t)OUT_F * KAUG];   // 19 MB

// ---------------- small PTX helpers (all base-sm_80+ features) -------------
__device__ __forceinline__ uint32_t smem_u32(const void* p) {
    uint32_t a;
    asm("{ .reg .u64 t; cvta.to.shared.u64 t, %1; cvt.u32.u64 %0, t; }" : "=r"(a) : "l"(p));
    return a;
}
__device__ __forceinline__ void cp16(uint32_t dst, const void* src) {
    asm volatile("cp.async.cg.shared.global [%0], [%1], 16;" :: "r"(dst), "l"(src));
}
#define CP_COMMIT() asm volatile("cp.async.commit_group;" ::: "memory")
#define CP_WAIT_2() asm volatile("cp.async.wait_group 2;" ::: "memory")

__device__ __forceinline__ void ldsm4(uint32_t& r0, uint32_t& r1, uint32_t& r2,
                                      uint32_t& r3, uint32_t addr) {
    asm volatile("ldmatrix.sync.aligned.m8n8.x4.shared.b16 {%0,%1,%2,%3}, [%4];"
                 : "=r"(r0), "=r"(r1), "=r"(r2), "=r"(r3) : "r"(addr));
}
__device__ __forceinline__ void mma16816(float& d0, float& d1, float& d2, float& d3,
                                         uint32_t a0, uint32_t a1, uint32_t a2, uint32_t a3,
                                         uint32_t b0, uint32_t b1) {
    asm volatile(
        "mma.sync.aligned.m16n8k16.row.col.f32.bf16.bf16.f32 "
        "{%0,%1,%2,%3}, {%4,%5,%6,%7}, {%8,%9}, {%0,%1,%2,%3};"
        : "+f"(d0), "+f"(d1), "+f"(d2), "+f"(d3)
        : "r"(a0), "r"(a1), "r"(a2), "r"(a3), "r"(b0), "r"(b1));
}
// 64-byte-wide smem rows; XOR swizzle keeps ldmatrix & cp.async conflict-free.
// col c (16B units) -> (c ^ ((r>>1)&3)).  k16 step = c+2 = swizzled-offset ^ 0x20.
__device__ __forceinline__ uint32_t swz(int r, int c) {
    return (uint32_t)(r * 64 + ((c ^ ((r >> 1) & 3)) << 4));
}

// ---------------- basis (identical math to passing Round-1 kernel) --------
__device__ __forceinline__ void aug_features(float xr, float* bb) {
    float xc = fminf(fmaxf(xr, -2.0f), 2.0f);
    float g[15];
#pragma unroll
    for (int m = 0; m < 15; ++m) g[m] = fmaf((float)m, 2.0f / 14.0f, -1.0f);
    float b[14];
#pragma unroll
    for (int m = 0; m < 14; ++m) b[m] = (xc >= g[m] && xc < g[m + 1]) ? 1.0f : 0.0f;
#pragma unroll
    for (int k = 1; k <= 3; ++k) {
        float inv = 7.0f / (float)k;
#pragma unroll
        for (int m = 0; m < 14 - k; ++m)
            b[m] = (xc - g[m]) * inv * b[m] + (g[m + k + 1] - xc) * inv * b[m + 1];
    }
    bb[0] = xr;
#pragma unroll
    for (int j = 0; j < 11; ++j) bb[1 + j] = b[j];
}

// ---------------- P1: activations -> split-bf16 augmented A ---------------
__global__ __launch_bounds__(256) void prep_A(const float* __restrict__ x) {
    int idx = blockIdx.x * 256 + threadIdx.x;        // (m, i)
    int m = idx >> 9, i = idx & 511;
    float bb[NFEAT];
    aug_features(x[idx], bb);
    unsigned short s[NFEAT * SLOTS];
#pragma unroll
    for (int c = 0; c < NFEAT; ++c) {
        float v = bb[c];
        __nv_bfloat16 h = __float2bfloat16(v);
        __nv_bfloat16 l = __float2bfloat16(v - __bfloat162float(h));
        unsigned short hb = __bfloat16_as_ushort(h), lb = __bfloat16_as_ushort(l);
        s[3 * c + 0] = hb;  s[3 * c + 1] = lb;  s[3 * c + 2] = hb;   // A: [hi, lo, hi]
    }
    unsigned long long* dst =
        (unsigned long long*)(g_A + (size_t)m * KAUG + (size_t)i * (NFEAT * SLOTS));
#pragma unroll
    for (int j = 0; j < 9; ++j)
        dst[j] = (unsigned long long)s[4 * j] |
                 ((unsigned long long)s[4 * j + 1] << 16) |
                 ((unsigned long long)s[4 * j + 2] << 32) |
                 ((unsigned long long)s[4 * j + 3] << 48);
}

// ---------------- P2: weights -> split-bf16 augmented B -------------------
__global__ __launch_bounds__(256) void prep_B(const float* __restrict__ bw,
                                              const float* __restrict__ sw) {
    int idx = blockIdx.x * 256 + threadIdx.x;        // (o, i)
    int o = idx >> 9, i = idx & 511;
    float v[NFEAT];
    v[0] = bw[(size_t)o * IN_F + i];
#pragma unroll
    for (int j = 0; j < 11; ++j) v[1 + j] = sw[((size_t)o * IN_F + i) * 11 + j];
    unsigned short s[NFEAT * SLOTS];
#pragma unroll
    for (int c = 0; c < NFEAT; ++c) {
        __nv_bfloat16 h = __float2bfloat16(v[c]);
        __nv_bfloat16 l = __float2bfloat16(v[c] - __bfloat162float(h));
        unsigned short hb = __bfloat16_as_ushort(h), lb = __bfloat16_as_ushort(l);
        s[3 * c + 0] = hb;  s[3 * c + 1] = hb;  s[3 * c + 2] = lb;   // B: [hi, hi, lo]
    }
    unsigned long long* dst =
        (unsigned long long*)(g_B + (size_t)o * KAUG + (size_t)i * (NFEAT * SLOTS));
#pragma unroll
    for (int j = 0; j < 9; ++j)
        dst[j] = (unsigned long long)s[4 * j] |
                 ((unsigned long long)s[4 * j + 1] << 16) |
                 ((unsigned long long)s[4 * j + 2] << 32) |
                 ((unsigned long long)s[4 * j + 3] << 48);
}

// ---------------- G: mma.sync bf16 GEMM, 4-stage cp.async pipeline --------
// CTA 128x256, 8 warps in 2(M) x 4(N), warp tile 64x64.
__global__ __launch_bounds__(256, 1) void kan_gemm(float* __restrict__ out) {
    extern __shared__ unsigned char smem[];
    const uint32_t sbase = smem_u32(smem);
    const int tid  = threadIdx.x;
    const int lane = tid & 31;
    const int wid  = tid >> 5;
    const int warpM = wid & 1;          // 0..1  -> 64-row slice
    const int warpN = wid >> 1;         // 0..3  -> 64-col slice
    const int mBase = blockIdx.y * M_TILE;
    const int nBase = blockIdx.x * N_TILE;

    const char* Ag = (const char*)(g_A + (size_t)mBase * KAUG);
    const char* Bg = (const char*)(g_B + (size_t)nBase * KAUG);

    // ---- per-thread cp.async coordinates (16B granules, 4 per 64B row) ----
    const int rA = tid >> 2, cA = tid & 3;            // A: 512 granules, 2/thread
    const char* aSrc0 = Ag + (size_t)rA        * ROWB + cA * 16;
    const char* aSrc1 = Ag + (size_t)(rA + 64) * ROWB + cA * 16;
    const uint32_t aDst0 = swz(rA, cA), aDst1 = swz(rA + 64, cA);
    const char* bSrc0 = Bg + (size_t)rA         * ROWB + cA * 16;  // B: 1024, 4/thread
    const char* bSrc1 = Bg + (size_t)(rA +  64) * ROWB + cA * 16;
    const char* bSrc2 = Bg + (size_t)(rA + 128) * ROWB + cA * 16;
    const char* bSrc3 = Bg + (size_t)(rA + 192) * ROWB + cA * 16;
    const uint32_t bDst0 = 8192u + swz(rA, cA),       bDst1 = 8192u + swz(rA + 64, cA);
    const uint32_t bDst2 = 8192u + swz(rA + 128, cA), bDst3 = 8192u + swz(rA + 192, cA);

    auto load_stage = [&](int ch) {
        const uint32_t st = sbase + (uint32_t)(ch & (STG - 1)) * STAGE_BYTES;
        const size_t off = (size_t)ch * 64;
        cp16(st + aDst0, aSrc0 + off);  cp16(st + aDst1, aSrc1 + off);
        cp16(st + bDst0, bSrc0 + off);  cp16(st + bDst1, bSrc1 + off);
        cp16(st + bDst2, bSrc2 + off);  cp16(st + bDst3, bSrc3 + off);
    };

    // ---- ldmatrix lane addressing ----
    const int lr = lane & 15;           // fragment row within 16
    const int lc = lane >> 4;           // 16B column block (0/1) => k half
    uint32_t aOff[4], bOff[4];
#pragma unroll
    for (int t = 0; t < 4; ++t) {
        aOff[t] = swz(warpM * 64 + t * 16 + lr, lc);
        bOff[t] = 8192u + swz(warpN * 64 + t * 16 + lr, lc);
    }

    float acc[4][8][4];
#pragma unroll
    for (int mt = 0; mt < 4; ++mt)
#pragma unroll
        for (int nt = 0; nt < 8; ++nt)
#pragma unroll
            for (int q = 0; q < 4; ++q) acc[mt][nt][q] = 0.0f;

    for (int i = 0; i < STG - 1; ++i) { load_stage(i); CP_COMMIT(); }

#pragma unroll 1
    for (int i = 0; i < NCH; ++i) {
        CP_WAIT_2();
        __syncthreads();
        const int nc = i + STG - 1;
        if (nc < NCH) load_stage(nc);
        CP_COMMIT();

        const uint32_t st = sbase + (uint32_t)(i & (STG - 1)) * STAGE_BYTES;
#pragma unroll
        for (int ks = 0; ks < 2; ++ks) {
            const uint32_t kadd = (uint32_t)ks << 5;    // k16 step: XOR 0x20 (swizzle!)
            uint32_t a[4][4], b[4][4];
#pragma unroll
            for (int t = 0; t < 4; ++t)
                ldsm4(a[t][0], a[t][1], a[t][2], a[t][3], st + (aOff[t] ^ kadd));
#pragma unroll
            for (int t = 0; t < 4; ++t)
                ldsm4(b[t][0], b[t][1], b[t][2], b[t][3], st + (bOff[t] ^ kadd));
#pragma unroll
            for (int mt = 0; mt < 4; ++mt)
#pragma unroll
                for (int t = 0; t < 4; ++t) {
                    // n8 tile 2t: b regs {0,2};  n8 tile 2t+1: b regs {1,3}
                    mma16816(acc[mt][2*t][0], acc[mt][2*t][1], acc[mt][2*t][2], acc[mt][2*t][3],
                             a[mt][0], a[mt][1], a[mt][2], a[mt][3], b[t][0], b[t][2]);
                    mma16816(acc[mt][2*t+1][0], acc[mt][2*t+1][1], acc[mt][2*t+1][2], acc[mt][2*t+1][3],
                             a[mt][0], a[mt][1], a[mt][2], a[mt][3], b[t][1], b[t][3]);
                }
        }
        __syncthreads();
    }

    // ---- epilogue: direct STG of register accumulators --------------------
    const int mRow = mBase + warpM * 64 + (lane >> 2);
    const int nCol = nBase + warpN * 64 + (lane & 3) * 2;
#pragma unroll
    for (int mt = 0; mt < 4; ++mt) {
        float* r0 = out + (size_t)(mRow + mt * 16)     * OUT_F + nCol;
        float* r1 = out + (size_t)(mRow + mt * 16 + 8) * OUT_F + nCol;
#pragma unroll
        for (int nt = 0; nt < 8; ++nt) {
            *(float2*)(r0 + nt * 8) = make_float2(acc[mt][nt][0], acc[mt][nt][1]);
            *(float2*)(r1 + nt * 8) = make_float2(acc[mt][nt][2], acc[mt][nt][3]);
        }
    }
}

// ---------------- launch ---------------------------------------------------
extern "C" void kernel_launch(void* const* d_in, const int* in_sizes, int n_in,
                              void* d_out, int out_size) {
    const float* x  = (const float*)d_in[0];
    const float* bw = (const float*)d_in[1];
    const float* sw = (const float*)d_in[2];
    float* out = (float*)d_out;

    cudaFuncSetAttribute(kan_gemm, cudaFuncAttributeMaxDynamicSharedMemorySize,
                         SMEM_TOTAL);

    prep_A<<<(NBAT * IN_F) / 256, 256>>>(x);
    prep_B<<<(OUT_F * IN_F) / 256, 256>>>(bw, sw);
    kan_gemm<<<dim3(OUT_F / N_TILE, NBAT / M_TILE), 256, SMEM_TOTAL>>>(out);
}

// round 7
// speedup vs baseline: 2.8224x; 1.2300x over previous
#include <cuda_runtime.h>
#include <cuda_bf16.h>
#include <cstdint>

#define IN_F   512
#define OUT_F  512
#define NBAT   8192
#define NFEAT  12                      // 1 raw x + 11 spline bases
#define SLOTS  3                       // bf16 split: A=[hi,lo,hi], B=[hi,hi,lo]
#define KAUG   (IN_F * NFEAT * SLOTS)  // 18432
#define KCH    64                      // bf16 elems per pipeline chunk (128 B)
#define NCH    (KAUG / KCH)            // 288
#define STG    4
#define M_TILE 128
#define N_TILE 256
#define ROWB   (KAUG * 2)              // global row stride in bytes
#define A_STAGE (M_TILE * 128)                    // 16 KB
#define B_STAGE (N_TILE * 128)                    // 32 KB
#define STAGE_BYTES (A_STAGE + B_STAGE)           // 49152
#define SMEM_TOTAL  (STG * STAGE_BYTES)           // 196608

// ---------------- scratch (device globals: allocation-free) ----------------
__device__ __nv_bfloat16 g_A[(size_t)NBAT * KAUG];    // 302 MB
__device__ __nv_bfloat16 g_B[(size_t)OUT_F * KAUG];   // 19 MB

// ---------------- PTX helpers (base-sm_80+ features only) ------------------
__device__ __forceinline__ uint32_t smem_u32(const void* p) {
    uint32_t a;
    asm("{ .reg .u64 t; cvta.to.shared.u64 t, %1; cvt.u32.u64 %0, t; }" : "=r"(a) : "l"(p));
    return a;
}
__device__ __forceinline__ void cp16(uint32_t dst, const void* src) {
    asm volatile("cp.async.cg.shared.global [%0], [%1], 16;" :: "r"(dst), "l"(src));
}
#define CP_COMMIT() asm volatile("cp.async.commit_group;" ::: "memory")
#define CP_WAIT_2() asm volatile("cp.async.wait_group 2;" ::: "memory")

__device__ __forceinline__ void ldsm4(uint32_t& r0, uint32_t& r1, uint32_t& r2,
                                      uint32_t& r3, uint32_t addr) {
    asm volatile("ldmatrix.sync.aligned.m8n8.x4.shared.b16 {%0,%1,%2,%3}, [%4];"
                 : "=r"(r0), "=r"(r1), "=r"(r2), "=r"(r3) : "r"(addr));
}
__device__ __forceinline__ void mma16816(float& d0, float& d1, float& d2, float& d3,
                                         uint32_t a0, uint32_t a1, uint32_t a2, uint32_t a3,
                                         uint32_t b0, uint32_t b1) {
    asm volatile(
        "mma.sync.aligned.m16n8k16.row.col.f32.bf16.bf16.f32 "
        "{%0,%1,%2,%3}, {%4,%5,%6,%7}, {%8,%9}, {%0,%1,%2,%3};"
        : "+f"(d0), "+f"(d1), "+f"(d2), "+f"(d3)
        : "r"(a0), "r"(a1), "r"(a2), "r"(a3), "r"(b0), "r"(b1));
}
// 128-byte smem rows, 8 granules of 16B, XOR-(r&7) swizzle (conflict-free both ways).
// k16 step s advances col by 2 granules: carry-free -> pure XOR of (s<<5) on the addr.
__device__ __forceinline__ uint32_t swz(int r, int c) {
    return (uint32_t)(r * 128 + ((c ^ (r & 7)) << 4));
}

// ---------------- basis (identical math to the passing kernels) ------------
__device__ __forceinline__ void aug_features(float xr, float* bb) {
    float xc = fminf(fmaxf(xr, -2.0f), 2.0f);
    float g[15];
#pragma unroll
    for (int m = 0; m < 15; ++m) g[m] = fmaf((float)m, 2.0f / 14.0f, -1.0f);
    float b[14];
#pragma unroll
    for (int m = 0; m < 14; ++m) b[m] = (xc >= g[m] && xc < g[m + 1]) ? 1.0f : 0.0f;
#pragma unroll
    for (int k = 1; k <= 3; ++k) {
        float inv = 7.0f / (float)k;
#pragma unroll
        for (int m = 0; m < 14 - k; ++m)
            b[m] = (xc - g[m]) * inv * b[m] + (g[m + k + 1] - xc) * inv * b[m + 1];
    }
    bb[0] = xr;
#pragma unroll
    for (int j = 0; j < 11; ++j) bb[1 + j] = b[j];
}

// ---------------- P1: activations -> split-bf16 A (2 features/thread) -----
__global__ __launch_bounds__(256) void prep_A(const float* __restrict__ x) {
    int p  = blockIdx.x * 256 + threadIdx.x;         // pair index
    int m  = p >> 8;
    int ip = (p & 255) * 2;                          // even feature index

    float2 xv = *(const float2*)&x[(size_t)m * IN_F + ip];
    uint32_t w[36];                                  // 72 bf16 packed as 36 u32
#pragma unroll
    for (int f = 0; f < 2; ++f) {
        float bb[NFEAT];
        aug_features(f ? xv.y : xv.x, bb);
        unsigned short s[NFEAT * SLOTS];
#pragma unroll
        for (int c = 0; c < NFEAT; ++c) {
            float v = bb[c];
            __nv_bfloat16 h = __float2bfloat16(v);
            __nv_bfloat16 l = __float2bfloat16(v - __bfloat162float(h));
            unsigned short hb = __bfloat16_as_ushort(h), lb = __bfloat16_as_ushort(l);
            s[3 * c + 0] = hb;  s[3 * c + 1] = lb;  s[3 * c + 2] = hb;  // A: [hi,lo,hi]
        }
#pragma unroll
        for (int k = 0; k < 18; ++k)
            w[f * 18 + k] = (uint32_t)s[2 * k] | ((uint32_t)s[2 * k + 1] << 16);
    }
    // 144 contiguous bytes, 16B-aligned (offset = 144 * (p-within-row pair))
    uint4* dst = (uint4*)(g_A + (size_t)m * KAUG + (size_t)ip * (NFEAT * SLOTS));
#pragma unroll
    for (int j = 0; j < 9; ++j)
        dst[j] = make_uint4(w[4 * j], w[4 * j + 1], w[4 * j + 2], w[4 * j + 3]);
}

// ---------------- P2: weights -> split-bf16 B ------------------------------
__global__ __launch_bounds__(256) void prep_B(const float* __restrict__ bw,
                                              const float* __restrict__ sw) {
    int idx = blockIdx.x * 256 + threadIdx.x;        // (o, i)
    int o = idx >> 9, i = idx & 511;
    float v[NFEAT];
    v[0] = bw[(size_t)o * IN_F + i];
#pragma unroll
    for (int j = 0; j < 11; ++j) v[1 + j] = sw[((size_t)o * IN_F + i) * 11 + j];
    unsigned short s[NFEAT * SLOTS];
#pragma unroll
    for (int c = 0; c < NFEAT; ++c) {
        __nv_bfloat16 h = __float2bfloat16(v[c]);
        __nv_bfloat16 l = __float2bfloat16(v[c] - __bfloat162float(h));
        unsigned short hb = __bfloat16_as_ushort(h), lb = __bfloat16_as_ushort(l);
        s[3 * c + 0] = hb;  s[3 * c + 1] = hb;  s[3 * c + 2] = lb;     // B: [hi,hi,lo]
    }
    unsigned long long* dst =
        (unsigned long long*)(g_B + (size_t)o * KAUG + (size_t)i * (NFEAT * SLOTS));
#pragma unroll
    for (int j = 0; j < 9; ++j)
        dst[j] = (unsigned long long)s[4 * j] |
                 ((unsigned long long)s[4 * j + 1] << 16) |
                 ((unsigned long long)s[4 * j + 2] << 32) |
                 ((unsigned long long)s[4 * j + 3] << 48);
}

// ---------------- G: mma.sync bf16 GEMM, k64 chunks, 4 stages --------------
// CTA 128x256, 8 warps 2(M) x 4(N), warp tile 64x64, one barrier per chunk.
__global__ __launch_bounds__(256, 1) void kan_gemm(float* __restrict__ out) {
    extern __shared__ __align__(1024) unsigned char smem[];
    const uint32_t sbase = smem_u32(smem);
    const int tid  = threadIdx.x;
    const int lane = tid & 31;
    const int wid  = tid >> 5;
    const int warpM = wid & 1;
    const int warpN = wid >> 1;
    const int mBase = blockIdx.y * M_TILE;
    const int nBase = blockIdx.x * N_TILE;

    const char* Ag = (const char*)(g_A + (size_t)mBase * KAUG);
    const char* Bg = (const char*)(g_B + (size_t)nBase * KAUG);

    // ---- cp.async coords: granule g = r*8+c handled by thread t = g&255 ----
    const int gr = tid >> 3, gc = tid & 7;
    const char* aSrc[4];  uint32_t aDst[4];
#pragma unroll
    for (int j = 0; j < 4; ++j) {                     // A: 1024 granules
        int r = gr + 32 * j;
        aSrc[j] = Ag + (size_t)r * ROWB + gc * 16;
        aDst[j] = swz(r, gc);
    }
    const char* bSrc[8];  uint32_t bDst[8];
#pragma unroll
    for (int j = 0; j < 8; ++j) {                     // B: 2048 granules
        int r = gr + 32 * j;
        bSrc[j] = Bg + (size_t)r * ROWB + gc * 16;
        bDst[j] = (uint32_t)A_STAGE + swz(r, gc);
    }

    auto load_stage = [&](int ch) {
        const uint32_t st = sbase + (uint32_t)(ch & (STG - 1)) * STAGE_BYTES;
        const size_t off = (size_t)ch * 128;
#pragma unroll
        for (int j = 0; j < 4; ++j) cp16(st + aDst[j], aSrc[j] + off);
#pragma unroll
        for (int j = 0; j < 8; ++j) cp16(st + bDst[j], bSrc[j] + off);
    };

    // ---- ldmatrix lane addressing (k-step advance = XOR (s<<5)) -----------
    const int lr = lane & 15;
    const int lc = lane >> 4;
    uint32_t aOff[4], bOff[4];
#pragma unroll
    for (int t = 0; t < 4; ++t) {
        aOff[t] = swz(warpM * 64 + t * 16 + lr, lc);
        bOff[t] = (uint32_t)A_STAGE + swz(warpN * 64 + t * 16 + lr, lc);
    }

    float acc[4][8][4];
#pragma unroll
    for (int mt = 0; mt < 4; ++mt)
#pragma unroll
        for (int nt = 0; nt < 8; ++nt)
#pragma unroll
            for (int q = 0; q < 4; ++q) acc[mt][nt][q] = 0.0f;

    for (int i = 0; i < STG - 1; ++i) { load_stage(i); CP_COMMIT(); }

#pragma unroll 1
    for (int i = 0; i < NCH; ++i) {
        CP_WAIT_2();                 // chunk i resident
        __syncthreads();             // also: all warps done with slot being reloaded
        const int nc = i + STG - 1;
        if (nc < NCH) load_stage(nc);
        CP_COMMIT();

        const uint32_t st = sbase + (uint32_t)(i & (STG - 1)) * STAGE_BYTES;

        uint32_t a[2][4][4], b[2][4][4];
#pragma unroll
        for (int t = 0; t < 4; ++t) {                 // k-step 0 frags
            ldsm4(a[0][t][0], a[0][t][1], a[0][t][2], a[0][t][3], st + aOff[t]);
            ldsm4(b[0][t][0], b[0][t][1], b[0][t][2], b[0][t][3], st + bOff[t]);
        }
#pragma unroll
        for (int s = 0; s < 4; ++s) {
            const int cur = s & 1, nxt = cur ^ 1;
            if (s < 3) {
                const uint32_t kx = (uint32_t)(s + 1) << 5;
#pragma unroll
                for (int t = 0; t < 4; ++t) {
                    ldsm4(a[nxt][t][0], a[nxt][t][1], a[nxt][t][2], a[nxt][t][3],
                          st + (aOff[t] ^ kx));
                    ldsm4(b[nxt][t][0], b[nxt][t][1], b[nxt][t][2], b[nxt][t][3],
                          st + (bOff[t] ^ kx));
                }
            }
#pragma unroll
            for (int mt = 0; mt < 4; ++mt)
#pragma unroll
                for (int t = 0; t < 4; ++t) {
                    mma16816(acc[mt][2*t][0], acc[mt][2*t][1], acc[mt][2*t][2], acc[mt][2*t][3],
                             a[cur][mt][0], a[cur][mt][1], a[cur][mt][2], a[cur][mt][3],
                             b[cur][t][0], b[cur][t][2]);
                    mma16816(acc[mt][2*t+1][0], acc[mt][2*t+1][1], acc[mt][2*t+1][2], acc[mt][2*t+1][3],
                             a[cur][mt][0], a[cur][mt][1], a[cur][mt][2], a[cur][mt][3],
                             b[cur][t][1], b[cur][t][3]);
                }
        }
    }

    // ---- epilogue: direct STG of register accumulators --------------------
    const int mRow = mBase + warpM * 64 + (lane >> 2);
    const int nCol = nBase + warpN * 64 + (lane & 3) * 2;
#pragma unroll
    for (int mt = 0; mt < 4; ++mt) {
        float* r0 = out + (size_t)(mRow + mt * 16)     * OUT_F + nCol;
        float* r1 = out + (size_t)(mRow + mt * 16 + 8) * OUT_F + nCol;
#pragma unroll
        for (int nt = 0; nt < 8; ++nt) {
            *(float2*)(r0 + nt * 8) = make_float2(acc[mt][nt][0], acc[mt][nt][1]);
            *(float2*)(r1 + nt * 8) = make_float2(acc[mt][nt][2], acc[mt][nt][3]);
        }
    }
}

// ---------------- launch ---------------------------------------------------
extern "C" void kernel_launch(void* const* d_in, const int* in_sizes, int n_in,
                              void* d_out, int out_size) {
    const float* x  = (const float*)d_in[0];
    const float* bw = (const float*)d_in[1];
    const float* sw = (const float*)d_in[2];
    float* out = (float*)d_out;

    cudaFuncSetAttribute(kan_gemm, cudaFuncAttributeMaxDynamicSharedMemorySize,
                         SMEM_TOTAL);

    prep_A<<<(NBAT * IN_F / 2) / 256, 256>>>(x);
    prep_B<<<(OUT_F * IN_F) / 256, 256>>>(bw, sw);
    kan_gemm<<<dim3(OUT_F / N_TILE, NBAT / M_TILE), 256, SMEM_TOTAL>>>(out);
}